// round 10
// baseline (speedup 1.0000x reference)
#include <cuda_runtime.h>
#include <cuda_bf16.h>
#include <math.h>

#define N_NODES 50000
#define N_PAD   50176    // 392*128, covers last gemm tile
#define N_EDGES 800000
#define F_IN    128
#define HF      128     // H*F
#define NHEADS  8
#define FPH     16
#define NEG_SLOPE 0.2f
#define CAP     64       // bucket capacity per dst (Poisson(16); P(>64)~2e-18)
#define SPILL_MAX 8192

// ---------------- scratch (static device globals; no allocation) ----------------
__device__ float    g_h[N_NODES * HF];        // projected features [N,128]
__device__ float    g_asrc[N_NODES * NHEADS]; // per-node src logits
__device__ float    g_adst[N_NODES * NHEADS]; // per-node dst logits
__device__ unsigned g_xh[N_PAD * 64];         // x hi split, bf16x2 (pad rows stay 0)
__device__ unsigned g_xl[N_PAD * 64];         // x lo split
__device__ unsigned g_wh[HF * 64];            // W hi split
__device__ unsigned g_wl[HF * 64];            // W lo split
__device__ int      g_cnt[N_NODES];           // bucket fill counts (reset by agg)
__device__ int      g_bkt[N_NODES * CAP];     // per-dst source buckets
__device__ int      g_spill[SPILL_MAX * 2];   // (dst,src) overflow pairs
__device__ int      g_spillcnt;               // reset by detect each run
__device__ int      g_is64;                   // 1 if edge_index is int64, 0 if int32

__device__ __forceinline__ float lrelu(float v) { return v >= 0.f ? v : NEG_SLOPE * v; }

__device__ __forceinline__ void cvt_split(float a, float b, unsigned& hi, unsigned& lo) {
    __nv_bfloat16 ah = __float2bfloat16(a), bh = __float2bfloat16(b);
    float ar = a - __bfloat162float(ah);
    float br = b - __bfloat162float(bh);
    __nv_bfloat16 al = __float2bfloat16(ar), bl = __float2bfloat16(br);
    hi = ((unsigned)__bfloat16_as_ushort(bh) << 16) | (unsigned)__bfloat16_as_ushort(ah);
    lo = ((unsigned)__bfloat16_as_ushort(bl) << 16) | (unsigned)__bfloat16_as_ushort(al);
}

// ---------------- detect dtype + reset spill counter ----------------
__global__ void detect_kernel(const void* ei_raw) {
    const long long* e64 = (const long long*)ei_raw;
    int lane = threadIdx.x;
    if (lane == 0) g_spillcnt = 0;
    int ok = 1;
    #pragma unroll
    for (int k = 0; k < 2; k++) {
        long long v = e64[lane * 2 + k];
        if (v < 0 || v >= N_NODES) ok = 0;
    }
    unsigned b = __ballot_sync(0xffffffffu, ok);
    if (lane == 0) g_is64 = (b == 0xffffffffu) ? 1 : 0;
}

// ---------------- convert: one-time bf16 hi/lo split of x and W ----------------
__global__ void convert_kernel(const float* __restrict__ x, const float* __restrict__ W) {
    int i = blockIdx.x * blockDim.x + threadIdx.x;   // float4 index
    if (i < N_NODES * F_IN / 4) {
        float4 v = *(const float4*)&x[i * 4];
        unsigned h0, l0, h1, l1;
        cvt_split(v.x, v.y, h0, l0);
        cvt_split(v.z, v.w, h1, l1);
        ((uint2*)g_xh)[i] = make_uint2(h0, h1);
        ((uint2*)g_xl)[i] = make_uint2(l0, l1);
    }
    if (i < HF * F_IN / 4) {
        float4 v = *(const float4*)&W[i * 4];
        unsigned h0, l0, h1, l1;
        cvt_split(v.x, v.y, h0, l0);
        cvt_split(v.z, v.w, h1, l1);
        ((uint2*)g_wh)[i] = make_uint2(h0, h1);
        ((uint2*)g_wl)[i] = make_uint2(l0, l1);
    }
}

// ---------------- tensor-core gemm: h = x @ W^T (bf16x3), fused logits ----------
#define SMS 20   // smem row stride in uints -> conflict-free frags

#define MMA_BF16(acc, a, b0, b1)                                              \
    asm volatile("mma.sync.aligned.m16n8k16.row.col.f32.bf16.bf16.f32 "       \
                 "{%0,%1,%2,%3}, {%4,%5,%6,%7}, {%8,%9}, {%0,%1,%2,%3};"      \
                 : "+f"((acc)[0]), "+f"((acc)[1]), "+f"((acc)[2]), "+f"((acc)[3]) \
                 : "r"((a)[0]), "r"((a)[1]), "r"((a)[2]), "r"((a)[3]),        \
                   "r"(b0), "r"(b1))

__global__ __launch_bounds__(256) void gemm_mma_kernel(
    const float* __restrict__ att_src, const float* __restrict__ att_dst)
{
    __shared__ unsigned Ah[128][SMS], Al[128][SMS];   // x tile   [m][k-pairs]
    __shared__ unsigned Bh[128][SMS], Bl[128][SMS];   // W tile   [n][k-pairs]

    int t    = threadIdx.x;
    int lane = t & 31;
    int wid  = t >> 5;
    int wr   = wid & 3;          // M group (32 rows)
    int wc   = wid >> 2;         // N group (64 cols)
    int q    = lane & 3;
    int gr   = lane >> 2;        // 0..7
    int m0   = blockIdx.x * 128;

    float acc[2][8][4];
    #pragma unroll
    for (int a = 0; a < 2; a++)
        #pragma unroll
        for (int b = 0; b < 8; b++)
            #pragma unroll
            for (int c = 0; c < 4; c++) acc[a][b][c] = 0.f;

    for (int ch = 0; ch < 4; ch++) {
        __syncthreads();
        // pure uint4 copy: 4 arrays x 128 rows x 4 uint4 = 2048 loads, 8/thread
        #pragma unroll
        for (int i = 0; i < 8; i++) {
            int idx = t + 256 * i;       // 0..2047
            int arr = idx >> 9;
            int rem = idx & 511;
            int row = rem >> 2;
            int u   = rem & 3;
            int goff = ch * 16 + u * 4;
            uint4 v;
            unsigned* dst;
            if (arr == 0)      { v = *(const uint4*)&g_xh[(m0 + row) * 64 + goff]; dst = &Ah[row][u * 4]; }
            else if (arr == 1) { v = *(const uint4*)&g_xl[(m0 + row) * 64 + goff]; dst = &Al[row][u * 4]; }
            else if (arr == 2) { v = *(const uint4*)&g_wh[row * 64 + goff];        dst = &Bh[row][u * 4]; }
            else               { v = *(const uint4*)&g_wl[row * 64 + goff];        dst = &Bl[row][u * 4]; }
            *(uint4*)dst = v;
        }
        __syncthreads();

        #pragma unroll
        for (int step = 0; step < 2; step++) {
            int kw = step * 8 + q;
            unsigned ah[2][4], al[2][4];
            #pragma unroll
            for (int mt = 0; mt < 2; mt++) {
                int r = wr * 32 + mt * 16 + gr;
                ah[mt][0] = Ah[r][kw];     ah[mt][1] = Ah[r + 8][kw];
                ah[mt][2] = Ah[r][kw + 4]; ah[mt][3] = Ah[r + 8][kw + 4];
                al[mt][0] = Al[r][kw];     al[mt][1] = Al[r + 8][kw];
                al[mt][2] = Al[r][kw + 4]; al[mt][3] = Al[r + 8][kw + 4];
            }
            #pragma unroll
            for (int nt = 0; nt < 8; nt++) {
                int n = wc * 64 + nt * 8 + gr;
                unsigned b0h = Bh[n][kw], b1h = Bh[n][kw + 4];
                unsigned b0l = Bl[n][kw], b1l = Bl[n][kw + 4];
                #pragma unroll
                for (int mt = 0; mt < 2; mt++) {
                    MMA_BF16(acc[mt][nt], ah[mt], b0h, b1h);
                    MMA_BF16(acc[mt][nt], ah[mt], b0l, b1l);
                    MMA_BF16(acc[mt][nt], al[mt], b0h, b1h);
                }
            }
        }
    }

    // epilogue: store h + fused per-head logit dot products
    float2 asv[8], adv[8];
    #pragma unroll
    for (int nt = 0; nt < 8; nt++) {
        int head = wc * 4 + (nt >> 1);
        int fc   = (nt & 1) * 8 + q * 2;
        asv[nt] = *(const float2*)&att_src[head * FPH + fc];
        adv[nt] = *(const float2*)&att_dst[head * FPH + fc];
    }

    #pragma unroll
    for (int mt = 0; mt < 2; mt++) {
        int m = m0 + wr * 32 + mt * 16 + gr;
        bool ok0 = (m < N_NODES), ok1 = (m + 8 < N_NODES);
        float ps0[4] = {0,0,0,0}, ps1[4] = {0,0,0,0};
        float pd0[4] = {0,0,0,0}, pd1[4] = {0,0,0,0};
        #pragma unroll
        for (int nt = 0; nt < 8; nt++) {
            float* c = acc[mt][nt];
            int n = wc * 64 + nt * 8 + q * 2;
            if (ok0) *(float2*)&g_h[m * HF + n]       = make_float2(c[0], c[1]);
            if (ok1) *(float2*)&g_h[(m + 8) * HF + n] = make_float2(c[2], c[3]);
            int hh = nt >> 1;
            ps0[hh] += c[0] * asv[nt].x + c[1] * asv[nt].y;
            pd0[hh] += c[0] * adv[nt].x + c[1] * adv[nt].y;
            ps1[hh] += c[2] * asv[nt].x + c[3] * asv[nt].y;
            pd1[hh] += c[2] * adv[nt].x + c[3] * adv[nt].y;
        }
        #pragma unroll
        for (int hh = 0; hh < 4; hh++) {
            ps0[hh] += __shfl_xor_sync(0xffffffffu, ps0[hh], 1);
            ps0[hh] += __shfl_xor_sync(0xffffffffu, ps0[hh], 2);
            pd0[hh] += __shfl_xor_sync(0xffffffffu, pd0[hh], 1);
            pd0[hh] += __shfl_xor_sync(0xffffffffu, pd0[hh], 2);
            ps1[hh] += __shfl_xor_sync(0xffffffffu, ps1[hh], 1);
            ps1[hh] += __shfl_xor_sync(0xffffffffu, ps1[hh], 2);
            pd1[hh] += __shfl_xor_sync(0xffffffffu, pd1[hh], 1);
            pd1[hh] += __shfl_xor_sync(0xffffffffu, pd1[hh], 2);
        }
        if (q == 0) {
            if (ok0) {
                *(float4*)&g_asrc[m * NHEADS + wc * 4] = make_float4(ps0[0], ps0[1], ps0[2], ps0[3]);
                *(float4*)&g_adst[m * NHEADS + wc * 4] = make_float4(pd0[0], pd0[1], pd0[2], pd0[3]);
            }
            if (ok1) {
                *(float4*)&g_asrc[(m + 8) * NHEADS + wc * 4] = make_float4(ps1[0], ps1[1], ps1[2], ps1[3]);
                *(float4*)&g_adst[(m + 8) * NHEADS + wc * 4] = make_float4(pd1[0], pd1[1], pd1[2], pd1[3]);
            }
        }
    }
}

// ---------------- scatter: one-pass bucketized CSR build -------------------------
__global__ void scatter_kernel(const void* __restrict__ ei) {
    int i = (blockIdx.x * blockDim.x + threadIdx.x) * 4;
    if (i >= N_EDGES) return;
    int s[4], d[4];
    if (g_is64) {
        const long long* p = (const long long*)ei;
        longlong2 sa = *(const longlong2*)&p[i];
        longlong2 sb = *(const longlong2*)&p[i + 2];
        longlong2 da = *(const longlong2*)&p[N_EDGES + i];
        longlong2 db = *(const longlong2*)&p[N_EDGES + i + 2];
        s[0] = (int)sa.x; s[1] = (int)sa.y; s[2] = (int)sb.x; s[3] = (int)sb.y;
        d[0] = (int)da.x; d[1] = (int)da.y; d[2] = (int)db.x; d[3] = (int)db.y;
    } else {
        const int* p = (const int*)ei;
        int4 sv = *(const int4*)&p[i];
        int4 dv = *(const int4*)&p[N_EDGES + i];
        s[0] = sv.x; s[1] = sv.y; s[2] = sv.z; s[3] = sv.w;
        d[0] = dv.x; d[1] = dv.y; d[2] = dv.z; d[3] = dv.w;
    }
    #pragma unroll
    for (int k = 0; k < 4; k++) {
        int pos = atomicAdd(&g_cnt[d[k]], 1);
        if (pos < CAP) {
            g_bkt[d[k] * CAP + pos] = s[k];
        } else {
            int sp = atomicAdd(&g_spillcnt, 1);
            if (sp < SPILL_MAX) {
                g_spill[sp * 2]     = d[k];
                g_spill[sp * 2 + 1] = s[k];
            }
        }
    }
}

// ---------------- agg: single-pass flash softmax + weighted gather ---------------
// one warp per destination node; bucket layout, spill fallback, self-resetting cnt.
__global__ __launch_bounds__(256) void agg_kernel(
    const float* __restrict__ bias, float* __restrict__ out)
{
    int warp = (blockIdx.x * blockDim.x + threadIdx.x) >> 5;
    int lane = threadIdx.x & 31;
    if (warp >= N_NODES) return;
    int n   = warp;
    int cnt = g_cnt[n];
    int beg = n * CAP;
    int end = beg + ((cnt < CAP) ? cnt : CAP);

    float ad = g_adst[n * NHEADS + (lane & 7)];
    int hsel = lane >> 2;

    float m = -INFINITY, ssum = 0.f;
    float4 acc = make_float4(0.f, 0.f, 0.f, 0.f);

    int j = beg;
    for (; j + 3 < end; j += 4) {
        int src0 = g_bkt[j],     src1 = g_bkt[j + 1];
        int src2 = g_bkt[j + 2], src3 = g_bkt[j + 3];
        float4 hv0 = *(const float4*)&g_h[src0 * HF + lane * 4];
        float4 hv1 = *(const float4*)&g_h[src1 * HF + lane * 4];
        float4 hv2 = *(const float4*)&g_h[src2 * HF + lane * 4];
        float4 hv3 = *(const float4*)&g_h[src3 * HF + lane * 4];
        float ev0 = (lane < 8) ? lrelu(g_asrc[src0 * NHEADS + lane] + ad) : 0.f;
        float ev1 = (lane < 8) ? lrelu(g_asrc[src1 * NHEADS + lane] + ad) : 0.f;
        float ev2 = (lane < 8) ? lrelu(g_asrc[src2 * NHEADS + lane] + ad) : 0.f;
        float ev3 = (lane < 8) ? lrelu(g_asrc[src3 * NHEADS + lane] + ad) : 0.f;
        float nm = fmaxf(fmaxf(m, fmaxf(ev0, ev1)), fmaxf(ev2, ev3));
        float f  = __expf(m - nm);
        float p0 = __expf(ev0 - nm);
        float p1 = __expf(ev1 - nm);
        float p2 = __expf(ev2 - nm);
        float p3 = __expf(ev3 - nm);
        ssum = ssum * f + (p0 + p1) + (p2 + p3);
        m = nm;
        float fb = __shfl_sync(0xffffffffu, f,  hsel);
        float a0 = __shfl_sync(0xffffffffu, p0, hsel);
        float a1 = __shfl_sync(0xffffffffu, p1, hsel);
        float a2 = __shfl_sync(0xffffffffu, p2, hsel);
        float a3 = __shfl_sync(0xffffffffu, p3, hsel);
        acc.x = acc.x * fb + a0 * hv0.x + a1 * hv1.x + a2 * hv2.x + a3 * hv3.x;
        acc.y = acc.y * fb + a0 * hv0.y + a1 * hv1.y + a2 * hv2.y + a3 * hv3.y;
        acc.z = acc.z * fb + a0 * hv0.z + a1 * hv1.z + a2 * hv2.z + a3 * hv3.z;
        acc.w = acc.w * fb + a0 * hv0.w + a1 * hv1.w + a2 * hv2.w + a3 * hv3.w;
    }
    for (; j < end; j++) {
        int src = g_bkt[j];
        float4 hv = *(const float4*)&g_h[src * HF + lane * 4];
        float ev = (lane < 8) ? lrelu(g_asrc[src * NHEADS + lane] + ad) : 0.f;
        float nm = fmaxf(m, ev);
        float f  = __expf(m - nm);
        float p  = __expf(ev - nm);
        ssum = ssum * f + p;
        m = nm;
        float fb = __shfl_sync(0xffffffffu, f, hsel);
        float a  = __shfl_sync(0xffffffffu, p, hsel);
        acc.x = acc.x * fb + a * hv.x;
        acc.y = acc.y * fb + a * hv.y;
        acc.z = acc.z * fb + a * hv.z;
        acc.w = acc.w * fb + a * hv.w;
    }

    // spill fallback (expected empty; correctness net for bucket overflow)
    int spn = g_spillcnt;
    if (spn > 0) {
        if (spn > SPILL_MAX) spn = SPILL_MAX;
        for (int k = 0; k < spn; k++) {
            if (g_spill[k * 2] != n) continue;
            int src = g_spill[k * 2 + 1];
            float4 hv = *(const float4*)&g_h[src * HF + lane * 4];
            float ev = (lane < 8) ? lrelu(g_asrc[src * NHEADS + lane] + ad) : 0.f;
            float nm = fmaxf(m, ev);
            float f  = __expf(m - nm);
            float p  = __expf(ev - nm);
            ssum = ssum * f + p;
            m = nm;
            float fb = __shfl_sync(0xffffffffu, f, hsel);
            float a  = __shfl_sync(0xffffffffu, p, hsel);
            acc.x = acc.x * fb + a * hv.x;
            acc.y = acc.y * fb + a * hv.y;
            acc.z = acc.z * fb + a * hv.z;
            acc.w = acc.w * fb + a * hv.w;
        }
    }

    if (lane == 0) g_cnt[n] = 0;   // reset for next graph replay

    float inv  = 1.f / (ssum + 1e-16f);
    float invb = __shfl_sync(0xffffffffu, inv, hsel);

    float4 bv = *(const float4*)&bias[lane * 4];
    float4 o = make_float4(acc.x * invb + bv.x, acc.y * invb + bv.y,
                           acc.z * invb + bv.z, acc.w * invb + bv.w);
    *(float4*)&out[n * HF + lane * 4] = o;
}

// ---------------- side stream + events (created once at static init) ------------
struct GraphStreams {
    cudaStream_t side;
    cudaEvent_t ev_fork, ev_join;
    GraphStreams() {
        cudaStreamCreateWithFlags(&side, cudaStreamNonBlocking);
        cudaEventCreateWithFlags(&ev_fork, cudaEventDisableTiming);
        cudaEventCreateWithFlags(&ev_join, cudaEventDisableTiming);
    }
};
static GraphStreams g_gs;

// ---------------- launch ----------------
extern "C" void kernel_launch(void* const* d_in, const int* in_sizes, int n_in,
                              void* d_out, int out_size)
{
    const float* x = nullptr;
    const float* W = nullptr;
    const void*  ei = nullptr;
    const float* p128[3] = {nullptr, nullptr, nullptr};
    int n128 = 0;
    for (int i = 0; i < n_in; i++) {
        long long sz = in_sizes[i];
        if (sz == (long long)N_NODES * F_IN)      x  = (const float*)d_in[i];
        else if (sz == (long long)HF * F_IN)      W  = (const float*)d_in[i];
        else if (sz == 2LL * N_EDGES)             ei = d_in[i];
        else if (sz == 128 && n128 < 3)           p128[n128++] = (const float*)d_in[i];
    }
    const float* att_src = p128[0];
    const float* att_dst = p128[1];
    const float* bias    = p128[2];
    float*       out     = (float*)d_out;

    // fork: convert + gemm on side stream, edge bucket build on main stream
    cudaEventRecord(g_gs.ev_fork, 0);
    cudaStreamWaitEvent(g_gs.side, g_gs.ev_fork, 0);
    convert_kernel<<<(N_NODES * F_IN / 4 + 255) / 256, 256, 0, g_gs.side>>>(x, W);
    gemm_mma_kernel<<<(N_NODES + 127) / 128, 256, 0, g_gs.side>>>(att_src, att_dst);
    cudaEventRecord(g_gs.ev_join, g_gs.side);

    detect_kernel<<<1, 32>>>(ei);
    scatter_kernel<<<(N_EDGES / 4 + 255) / 256, 256>>>(ei);

    // join, then aggregate
    cudaStreamWaitEvent(0, g_gs.ev_join, 0);
    agg_kernel<<<(N_NODES * 32 + 255) / 256, 256>>>(bias, out);
}

// round 11
// speedup vs baseline: 1.0036x; 1.0036x over previous
#include <cuda_runtime.h>
#include <cuda_bf16.h>
#include <cuda_fp16.h>
#include <math.h>

#define N_NODES 50000
#define N_PAD   50176    // 392*128, covers last gemm tile
#define N_EDGES 800000
#define F_IN    128
#define HF      128     // H*F
#define NHEADS  8
#define FPH     16
#define NEG_SLOPE 0.2f
#define CAP     64       // bucket capacity per dst (Poisson(16); P(>64)~2e-18)
#define SPILL_MAX 8192

// ---------------- scratch (static device globals; no allocation) ----------------
__device__ __half2  g_hh[N_NODES * 64];       // projected features [N,128] as fp16
__device__ float    g_asrc[N_NODES * NHEADS]; // per-node src logits
__device__ float    g_adst[N_NODES * NHEADS]; // per-node dst logits
__device__ unsigned g_xh[N_PAD * 64];         // x hi split, bf16x2 (pad rows stay 0)
__device__ unsigned g_xl[N_PAD * 64];         // x lo split
__device__ unsigned g_wh[HF * 64];            // W hi split
__device__ unsigned g_wl[HF * 64];            // W lo split
__device__ int      g_cnt[N_NODES];           // bucket fill counts (reset by agg)
__device__ int      g_bkt[N_NODES * CAP];     // per-dst source buckets
__device__ int      g_spill[SPILL_MAX * 2];   // (dst,src) overflow pairs
__device__ int      g_spillcnt;               // reset by detect each run
__device__ int      g_is64;                   // 1 if edge_index is int64, 0 if int32

__device__ __forceinline__ float lrelu(float v) { return v >= 0.f ? v : NEG_SLOPE * v; }

__device__ __forceinline__ void cvt_split(float a, float b, unsigned& hi, unsigned& lo) {
    __nv_bfloat16 ah = __float2bfloat16(a), bh = __float2bfloat16(b);
    float ar = a - __bfloat162float(ah);
    float br = b - __bfloat162float(bh);
    __nv_bfloat16 al = __float2bfloat16(ar), bl = __float2bfloat16(br);
    hi = ((unsigned)__bfloat16_as_ushort(bh) << 16) | (unsigned)__bfloat16_as_ushort(ah);
    lo = ((unsigned)__bfloat16_as_ushort(bl) << 16) | (unsigned)__bfloat16_as_ushort(al);
}

// ---------------- detect dtype + reset spill counter ----------------
__global__ void detect_kernel(const void* ei_raw) {
    const long long* e64 = (const long long*)ei_raw;
    int lane = threadIdx.x;
    if (lane == 0) g_spillcnt = 0;
    int ok = 1;
    #pragma unroll
    for (int k = 0; k < 2; k++) {
        long long v = e64[lane * 2 + k];
        if (v < 0 || v >= N_NODES) ok = 0;
    }
    unsigned b = __ballot_sync(0xffffffffu, ok);
    if (lane == 0) g_is64 = (b == 0xffffffffu) ? 1 : 0;
}

// ---------------- convert: one-time bf16 hi/lo split of x and W ----------------
__global__ void convert_kernel(const float* __restrict__ x, const float* __restrict__ W) {
    int i = blockIdx.x * blockDim.x + threadIdx.x;   // float4 index
    if (i < N_NODES * F_IN / 4) {
        float4 v = *(const float4*)&x[i * 4];
        unsigned h0, l0, h1, l1;
        cvt_split(v.x, v.y, h0, l0);
        cvt_split(v.z, v.w, h1, l1);
        ((uint2*)g_xh)[i] = make_uint2(h0, h1);
        ((uint2*)g_xl)[i] = make_uint2(l0, l1);
    }
    if (i < HF * F_IN / 4) {
        float4 v = *(const float4*)&W[i * 4];
        unsigned h0, l0, h1, l1;
        cvt_split(v.x, v.y, h0, l0);
        cvt_split(v.z, v.w, h1, l1);
        ((uint2*)g_wh)[i] = make_uint2(h0, h1);
        ((uint2*)g_wl)[i] = make_uint2(l0, l1);
    }
}

// ---------------- tensor-core gemm: h = x @ W^T (bf16x3), fused logits ----------
#define SMS 20   // smem row stride in uints -> conflict-free frags

#define MMA_BF16(acc, a, b0, b1)                                              \
    asm volatile("mma.sync.aligned.m16n8k16.row.col.f32.bf16.bf16.f32 "       \
                 "{%0,%1,%2,%3}, {%4,%5,%6,%7}, {%8,%9}, {%0,%1,%2,%3};"      \
                 : "+f"((acc)[0]), "+f"((acc)[1]), "+f"((acc)[2]), "+f"((acc)[3]) \
                 : "r"((a)[0]), "r"((a)[1]), "r"((a)[2]), "r"((a)[3]),        \
                   "r"(b0), "r"(b1))

__global__ __launch_bounds__(256) void gemm_mma_kernel(
    const float* __restrict__ att_src, const float* __restrict__ att_dst)
{
    __shared__ unsigned Ah[128][SMS], Al[128][SMS];   // x tile   [m][k-pairs]
    __shared__ unsigned Bh[128][SMS], Bl[128][SMS];   // W tile   [n][k-pairs]

    int t    = threadIdx.x;
    int lane = t & 31;
    int wid  = t >> 5;
    int wr   = wid & 3;          // M group (32 rows)
    int wc   = wid >> 2;         // N group (64 cols)
    int q    = lane & 3;
    int gr   = lane >> 2;        // 0..7
    int m0   = blockIdx.x * 128;

    float acc[2][8][4];
    #pragma unroll
    for (int a = 0; a < 2; a++)
        #pragma unroll
        for (int b = 0; b < 8; b++)
            #pragma unroll
            for (int c = 0; c < 4; c++) acc[a][b][c] = 0.f;

    for (int ch = 0; ch < 4; ch++) {
        __syncthreads();
        // pure uint4 copy: 4 arrays x 128 rows x 4 uint4 = 2048 loads, 8/thread
        #pragma unroll
        for (int i = 0; i < 8; i++) {
            int idx = t + 256 * i;       // 0..2047
            int arr = idx >> 9;
            int rem = idx & 511;
            int row = rem >> 2;
            int u   = rem & 3;
            int goff = ch * 16 + u * 4;
            uint4 v;
            unsigned* dst;
            if (arr == 0)      { v = *(const uint4*)&g_xh[(m0 + row) * 64 + goff]; dst = &Ah[row][u * 4]; }
            else if (arr == 1) { v = *(const uint4*)&g_xl[(m0 + row) * 64 + goff]; dst = &Al[row][u * 4]; }
            else if (arr == 2) { v = *(const uint4*)&g_wh[row * 64 + goff];        dst = &Bh[row][u * 4]; }
            else               { v = *(const uint4*)&g_wl[row * 64 + goff];        dst = &Bl[row][u * 4]; }
            *(uint4*)dst = v;
        }
        __syncthreads();

        #pragma unroll
        for (int step = 0; step < 2; step++) {
            int kw = step * 8 + q;
            unsigned ah[2][4], al[2][4];
            #pragma unroll
            for (int mt = 0; mt < 2; mt++) {
                int r = wr * 32 + mt * 16 + gr;
                ah[mt][0] = Ah[r][kw];     ah[mt][1] = Ah[r + 8][kw];
                ah[mt][2] = Ah[r][kw + 4]; ah[mt][3] = Ah[r + 8][kw + 4];
                al[mt][0] = Al[r][kw];     al[mt][1] = Al[r + 8][kw];
                al[mt][2] = Al[r][kw + 4]; al[mt][3] = Al[r + 8][kw + 4];
            }
            #pragma unroll
            for (int nt = 0; nt < 8; nt++) {
                int n = wc * 64 + nt * 8 + gr;
                unsigned b0h = Bh[n][kw], b1h = Bh[n][kw + 4];
                unsigned b0l = Bl[n][kw], b1l = Bl[n][kw + 4];
                #pragma unroll
                for (int mt = 0; mt < 2; mt++) {
                    MMA_BF16(acc[mt][nt], ah[mt], b0h, b1h);
                    MMA_BF16(acc[mt][nt], ah[mt], b0l, b1l);
                    MMA_BF16(acc[mt][nt], al[mt], b0h, b1h);
                }
            }
        }
    }

    // epilogue: store h (fp16) + fused per-head logit dot products (fp32)
    float2 asv[8], adv[8];
    #pragma unroll
    for (int nt = 0; nt < 8; nt++) {
        int head = wc * 4 + (nt >> 1);
        int fc   = (nt & 1) * 8 + q * 2;
        asv[nt] = *(const float2*)&att_src[head * FPH + fc];
        adv[nt] = *(const float2*)&att_dst[head * FPH + fc];
    }

    #pragma unroll
    for (int mt = 0; mt < 2; mt++) {
        int m = m0 + wr * 32 + mt * 16 + gr;
        bool ok0 = (m < N_NODES), ok1 = (m + 8 < N_NODES);
        float ps0[4] = {0,0,0,0}, ps1[4] = {0,0,0,0};
        float pd0[4] = {0,0,0,0}, pd1[4] = {0,0,0,0};
        #pragma unroll
        for (int nt = 0; nt < 8; nt++) {
            float* c = acc[mt][nt];
            int n = wc * 64 + nt * 8 + q * 2;   // even column pair
            if (ok0) g_hh[m * 64 + n / 2]       = __floats2half2_rn(c[0], c[1]);
            if (ok1) g_hh[(m + 8) * 64 + n / 2] = __floats2half2_rn(c[2], c[3]);
            int hh = nt >> 1;
            ps0[hh] += c[0] * asv[nt].x + c[1] * asv[nt].y;
            pd0[hh] += c[0] * adv[nt].x + c[1] * adv[nt].y;
            ps1[hh] += c[2] * asv[nt].x + c[3] * asv[nt].y;
            pd1[hh] += c[2] * adv[nt].x + c[3] * adv[nt].y;
        }
        #pragma unroll
        for (int hh = 0; hh < 4; hh++) {
            ps0[hh] += __shfl_xor_sync(0xffffffffu, ps0[hh], 1);
            ps0[hh] += __shfl_xor_sync(0xffffffffu, ps0[hh], 2);
            pd0[hh] += __shfl_xor_sync(0xffffffffu, pd0[hh], 1);
            pd0[hh] += __shfl_xor_sync(0xffffffffu, pd0[hh], 2);
            ps1[hh] += __shfl_xor_sync(0xffffffffu, ps1[hh], 1);
            ps1[hh] += __shfl_xor_sync(0xffffffffu, ps1[hh], 2);
            pd1[hh] += __shfl_xor_sync(0xffffffffu, pd1[hh], 1);
            pd1[hh] += __shfl_xor_sync(0xffffffffu, pd1[hh], 2);
        }
        if (q == 0) {
            if (ok0) {
                *(float4*)&g_asrc[m * NHEADS + wc * 4] = make_float4(ps0[0], ps0[1], ps0[2], ps0[3]);
                *(float4*)&g_adst[m * NHEADS + wc * 4] = make_float4(pd0[0], pd0[1], pd0[2], pd0[3]);
            }
            if (ok1) {
                *(float4*)&g_asrc[(m + 8) * NHEADS + wc * 4] = make_float4(ps1[0], ps1[1], ps1[2], ps1[3]);
                *(float4*)&g_adst[(m + 8) * NHEADS + wc * 4] = make_float4(pd1[0], pd1[1], pd1[2], pd1[3]);
            }
        }
    }
}

// ---------------- scatter: one-pass bucketized CSR build, 8 edges/thread ---------
__global__ void scatter_kernel(const void* __restrict__ ei) {
    int i = (blockIdx.x * blockDim.x + threadIdx.x) * 8;
    if (i >= N_EDGES) return;
    int s[8], d[8];
    if (g_is64) {
        const long long* p = (const long long*)ei;
        #pragma unroll
        for (int k = 0; k < 8; k += 2) {
            longlong2 sv = *(const longlong2*)&p[i + k];
            longlong2 dv = *(const longlong2*)&p[N_EDGES + i + k];
            s[k] = (int)sv.x; s[k + 1] = (int)sv.y;
            d[k] = (int)dv.x; d[k + 1] = (int)dv.y;
        }
    } else {
        const int* p = (const int*)ei;
        #pragma unroll
        for (int k = 0; k < 8; k += 4) {
            int4 sv = *(const int4*)&p[i + k];
            int4 dv = *(const int4*)&p[N_EDGES + i + k];
            s[k] = sv.x; s[k + 1] = sv.y; s[k + 2] = sv.z; s[k + 3] = sv.w;
            d[k] = dv.x; d[k + 1] = dv.y; d[k + 2] = dv.z; d[k + 3] = dv.w;
        }
    }
    int pos[8];
    #pragma unroll
    for (int k = 0; k < 8; k++) pos[k] = atomicAdd(&g_cnt[d[k]], 1);
    #pragma unroll
    for (int k = 0; k < 8; k++) {
        if (pos[k] < CAP) {
            g_bkt[d[k] * CAP + pos[k]] = s[k];
        } else {
            int sp = atomicAdd(&g_spillcnt, 1);
            if (sp < SPILL_MAX) {
                g_spill[sp * 2]     = d[k];
                g_spill[sp * 2 + 1] = s[k];
            }
        }
    }
}

// ---------------- agg: single-pass flash softmax + fp16 weighted gather ----------
__device__ __forceinline__ float4 load_h4(int src, int lane) {
    uint2 u = *(const uint2*)&g_hh[src * 64 + lane * 2];
    float2 f0 = __half22float2(*(__half2*)&u.x);
    float2 f1 = __half22float2(*(__half2*)&u.y);
    return make_float4(f0.x, f0.y, f1.x, f1.y);
}

__global__ __launch_bounds__(256) void agg_kernel(
    const float* __restrict__ bias, float* __restrict__ out)
{
    int warp = (blockIdx.x * blockDim.x + threadIdx.x) >> 5;
    int lane = threadIdx.x & 31;
    if (warp >= N_NODES) return;
    int n   = warp;
    int cnt = g_cnt[n];
    int beg = n * CAP;
    int end = beg + ((cnt < CAP) ? cnt : CAP);

    float ad = g_adst[n * NHEADS + (lane & 7)];
    int hsel = lane >> 2;

    float m = -INFINITY, ssum = 0.f;
    float4 acc = make_float4(0.f, 0.f, 0.f, 0.f);

    int j = beg;
    for (; j + 3 < end; j += 4) {
        int src0 = g_bkt[j],     src1 = g_bkt[j + 1];
        int src2 = g_bkt[j + 2], src3 = g_bkt[j + 3];
        float4 hv0 = load_h4(src0, lane);
        float4 hv1 = load_h4(src1, lane);
        float4 hv2 = load_h4(src2, lane);
        float4 hv3 = load_h4(src3, lane);
        float ev0 = (lane < 8) ? lrelu(g_asrc[src0 * NHEADS + lane] + ad) : 0.f;
        float ev1 = (lane < 8) ? lrelu(g_asrc[src1 * NHEADS + lane] + ad) : 0.f;
        float ev2 = (lane < 8) ? lrelu(g_asrc[src2 * NHEADS + lane] + ad) : 0.f;
        float ev3 = (lane < 8) ? lrelu(g_asrc[src3 * NHEADS + lane] + ad) : 0.f;
        float nm = fmaxf(fmaxf(m, fmaxf(ev0, ev1)), fmaxf(ev2, ev3));
        float f  = __expf(m - nm);
        float p0 = __expf(ev0 - nm);
        float p1 = __expf(ev1 - nm);
        float p2 = __expf(ev2 - nm);
        float p3 = __expf(ev3 - nm);
        ssum = ssum * f + (p0 + p1) + (p2 + p3);
        m = nm;
        float fb = __shfl_sync(0xffffffffu, f,  hsel);
        float a0 = __shfl_sync(0xffffffffu, p0, hsel);
        float a1 = __shfl_sync(0xffffffffu, p1, hsel);
        float a2 = __shfl_sync(0xffffffffu, p2, hsel);
        float a3 = __shfl_sync(0xffffffffu, p3, hsel);
        acc.x = acc.x * fb + a0 * hv0.x + a1 * hv1.x + a2 * hv2.x + a3 * hv3.x;
        acc.y = acc.y * fb + a0 * hv0.y + a1 * hv1.y + a2 * hv2.y + a3 * hv3.y;
        acc.z = acc.z * fb + a0 * hv0.z + a1 * hv1.z + a2 * hv2.z + a3 * hv3.z;
        acc.w = acc.w * fb + a0 * hv0.w + a1 * hv1.w + a2 * hv2.w + a3 * hv3.w;
    }
    for (; j < end; j++) {
        int src = g_bkt[j];
        float4 hv = load_h4(src, lane);
        float ev = (lane < 8) ? lrelu(g_asrc[src * NHEADS + lane] + ad) : 0.f;
        float nm = fmaxf(m, ev);
        float f  = __expf(m - nm);
        float p  = __expf(ev - nm);
        ssum = ssum * f + p;
        m = nm;
        float fb = __shfl_sync(0xffffffffu, f, hsel);
        float a  = __shfl_sync(0xffffffffu, p, hsel);
        acc.x = acc.x * fb + a * hv.x;
        acc.y = acc.y * fb + a * hv.y;
        acc.z = acc.z * fb + a * hv.z;
        acc.w = acc.w * fb + a * hv.w;
    }

    // spill fallback (expected empty; correctness net for bucket overflow)
    int spn = g_spillcnt;
    if (spn > 0) {
        if (spn > SPILL_MAX) spn = SPILL_MAX;
        for (int k = 0; k < spn; k++) {
            if (g_spill[k * 2] != n) continue;
            int src = g_spill[k * 2 + 1];
            float4 hv = load_h4(src, lane);
            float ev = (lane < 8) ? lrelu(g_asrc[src * NHEADS + lane] + ad) : 0.f;
            float nm = fmaxf(m, ev);
            float f  = __expf(m - nm);
            float p  = __expf(ev - nm);
            ssum = ssum * f + p;
            m = nm;
            float fb = __shfl_sync(0xffffffffu, f, hsel);
            float a  = __shfl_sync(0xffffffffu, p, hsel);
            acc.x = acc.x * fb + a * hv.x;
            acc.y = acc.y * fb + a * hv.y;
            acc.z = acc.z * fb + a * hv.z;
            acc.w = acc.w * fb + a * hv.w;
        }
    }

    if (lane == 0) g_cnt[n] = 0;   // reset for next graph replay

    float inv  = 1.f / (ssum + 1e-16f);
    float invb = __shfl_sync(0xffffffffu, inv, hsel);

    float4 bv = *(const float4*)&bias[lane * 4];
    float4 o = make_float4(acc.x * invb + bv.x, acc.y * invb + bv.y,
                           acc.z * invb + bv.z, acc.w * invb + bv.w);
    *(float4*)&out[n * HF + lane * 4] = o;
}

// ---------------- side stream + events (created once at static init) ------------
struct GraphStreams {
    cudaStream_t side;
    cudaEvent_t ev_fork, ev_join;
    GraphStreams() {
        cudaStreamCreateWithFlags(&side, cudaStreamNonBlocking);
        cudaEventCreateWithFlags(&ev_fork, cudaEventDisableTiming);
        cudaEventCreateWithFlags(&ev_join, cudaEventDisableTiming);
    }
};
static GraphStreams g_gs;

// ---------------- launch ----------------
extern "C" void kernel_launch(void* const* d_in, const int* in_sizes, int n_in,
                              void* d_out, int out_size)
{
    const float* x = nullptr;
    const float* W = nullptr;
    const void*  ei = nullptr;
    const float* p128[3] = {nullptr, nullptr, nullptr};
    int n128 = 0;
    for (int i = 0; i < n_in; i++) {
        long long sz = in_sizes[i];
        if (sz == (long long)N_NODES * F_IN)      x  = (const float*)d_in[i];
        else if (sz == (long long)HF * F_IN)      W  = (const float*)d_in[i];
        else if (sz == 2LL * N_EDGES)             ei = d_in[i];
        else if (sz == 128 && n128 < 3)           p128[n128++] = (const float*)d_in[i];
    }
    const float* att_src = p128[0];
    const float* att_dst = p128[1];
    const float* bias    = p128[2];
    float*       out     = (float*)d_out;

    // fork: convert + gemm on side stream, edge bucket build on main stream
    cudaEventRecord(g_gs.ev_fork, 0);
    cudaStreamWaitEvent(g_gs.side, g_gs.ev_fork, 0);
    convert_kernel<<<(N_NODES * F_IN / 4 + 255) / 256, 256, 0, g_gs.side>>>(x, W);
    gemm_mma_kernel<<<(N_NODES + 127) / 128, 256, 0, g_gs.side>>>(att_src, att_dst);
    cudaEventRecord(g_gs.ev_join, g_gs.side);

    detect_kernel<<<1, 32>>>(ei);
    scatter_kernel<<<(N_EDGES / 8 + 255) / 256, 256>>>(ei);

    // join, then aggregate
    cudaStreamWaitEvent(0, g_gs.ev_join, 0);
    agg_kernel<<<(N_NODES * 32 + 255) / 256, 256>>>(bias, out);
}